// round 15
// baseline (speedup 1.0000x reference)
#include <cuda_runtime.h>
#include <cuda_bf16.h>
#include <math.h>
#include <stdint.h>

#define NN    100000
#define FIN   512
#define HIDD  256
#define CCH   64
#define EMAX  3300000
#define MSORT 131072
#define SCHUNK 2048

typedef unsigned long long ull;

// packed fp32x2 FMA (Blackwell family-wide PTX; SASS FFMA2)
#define FMA_F32X2(d, a, b) \
    asm("fma.rn.f32x2 %0, %1, %2, %3;" : "=l"(d) : "l"(a), "l"(b), "l"(d))
#define PACK_DUP(out, v) \
    asm("mov.b64 %0, {%1, %1};" : "=l"(out) : "r"(__float_as_uint(v)))
#define PACK2(out, a, b) \
    asm("mov.b64 %0, {%1, %2};" : "=l"(out) : "r"(__float_as_uint(a)), "r"(__float_as_uint(b)))
#define UNPACK2(lo, hi, in) \
    asm("mov.b64 {%0, %1}, %2;" : "=r"(lo), "=r"(hi) : "l"(in))

// ---------------- scratch (device globals; no allocation) ----------------
__device__ float d_hw1 [(size_t)NN * HIDD];   // y1 = dinv[r] * (x@W1)[r]
__device__ float d_agg1[(size_t)NN * HIDD];
__device__ float d_hw2 [(size_t)NN * CCH];    // y2 = dinv[r] * (relu(agg1+b1)@W2)[r]
__device__ float d_x1  [(size_t)NN * CCH];
__device__ float d_score[NN];
__device__ int   d_degi[NN];
__device__ float d_dinv[NN];
__device__ int   d_rowptr[NN + 1];
__device__ int   d_fill[NN];
__device__ int   d_part[256];
__device__ int   d_csri[EMAX];         // src index only
__device__ float d_keys[MSORT];
__device__ int   d_vals[MSORT];
__device__ int   d_invp[NN];
__device__ float d_c1  [(size_t)NN * CCH];
__device__ float d_c2  [(size_t)NN * CCH];
__device__ int   d_is64;

// ---------------- edge dtype detect (1 warp) + grid-wide degree zero ----------------
__global__ void detect_kernel(const void* edges, long long nElemsI64, int n) {
    if (threadIdx.x == 0) {
        const long long* p = (const long long*)edges;
        int cnt = (int)(nElemsI64 < 256 ? nElemsI64 : 256);
        int ok = 1;
        for (int i = 0; i < cnt; i++) {
            long long v = p[i];
            if (v < 0 || v >= (long long)n) { ok = 0; break; }
        }
        d_is64 = ok;
    }
}

__global__ void zero_deg(int n) {
    int i = blockIdx.x * blockDim.x + threadIdx.x;
    if (i < n) d_degi[i] = 0;
}

__global__ void count_deg(const void* edges, int E) {
    int e = blockIdx.x * blockDim.x + threadIdx.x;
    if (e >= E) return;
    int d;
    if (d_is64) d = (int)((const long long*)edges)[e + E];
    else        d = ((const int*)edges)[e + E];
    atomicAdd(&d_degi[d], 1);
}

__global__ void compute_dinv(int n) {
    int i = blockIdx.x * blockDim.x + threadIdx.x;
    if (i < n) d_dinv[i] = rsqrtf((float)(d_degi[i] + 1));
}

// ---------------- SGEMM 1: y1 = dinv * (x @ W1)   64x64 tile, 128 thr ----------------
__global__ __launch_bounds__(128) void gemm1_kernel(const float* __restrict__ A,
                                                    const float* __restrict__ B,
                                                    float* __restrict__ C, int n) {
    __shared__ float As[8][68];
    __shared__ float Bs[8][68];
    int tid = threadIdx.x;
    int row0 = blockIdx.x * 64;
    int col0 = blockIdx.y * 64;
    int aRow = tid >> 1;            // 0..63
    int aK   = (tid & 1) << 2;      // 0 or 4
    int bK   = tid >> 4;            // 0..7
    int bCol = (tid & 15) << 2;     // 0..60
    int ty = tid >> 4;              // 0..7
    int tx = tid & 15;              // 0..15
    int cr4 = ty << 2;              // rows cr4..+3 and +32
    int cc4 = tx << 2;              // cols cc4..+3
    ull acc[8][2];
    #pragma unroll
    for (int i = 0; i < 8; i++) { acc[i][0] = 0ull; acc[i][1] = 0ull; }
    int gr = row0 + aRow;
    for (int k0 = 0; k0 < FIN; k0 += 8) {
        float4 av = make_float4(0,0,0,0);
        if (gr < n) av = *(const float4*)(A + (size_t)gr * FIN + k0 + aK);
        float4 bv = *(const float4*)(B + (size_t)(k0 + bK) * HIDD + col0 + bCol);
        As[aK+0][aRow] = av.x; As[aK+1][aRow] = av.y;
        As[aK+2][aRow] = av.z; As[aK+3][aRow] = av.w;
        *(float4*)&Bs[bK][bCol] = bv;
        __syncthreads();
        #pragma unroll
        for (int kk = 0; kk < 8; kk++) {
            float a[8];
            *(float4*)(a)     = *(const float4*)&As[kk][cr4];
            *(float4*)(a + 4) = *(const float4*)&As[kk][cr4 + 32];
            float4 bq = *(const float4*)&Bs[kk][cc4];
            ull b0, b1;
            PACK2(b0, bq.x, bq.y);
            PACK2(b1, bq.z, bq.w);
            #pragma unroll
            for (int i = 0; i < 8; i++) {
                ull ai;
                PACK_DUP(ai, a[i]);
                FMA_F32X2(acc[i][0], ai, b0);
                FMA_F32X2(acc[i][1], ai, b1);
            }
        }
        __syncthreads();
    }
    #pragma unroll
    for (int i = 0; i < 8; i++) {
        int r = row0 + cr4 + (i & 3) + ((i >> 2) << 5);   // +0 or +32
        if (r < n) {
            float dv = d_dinv[r];
            uint32_t lo, hi;
            float c0, c1v, c2v, c3v;
            UNPACK2(lo, hi, acc[i][0]); c0  = __uint_as_float(lo) * dv; c1v = __uint_as_float(hi) * dv;
            UNPACK2(lo, hi, acc[i][1]); c2v = __uint_as_float(lo) * dv; c3v = __uint_as_float(hi) * dv;
            *(float4*)(C + (size_t)r * HIDD + col0 + cc4) = make_float4(c0, c1v, c2v, c3v);
        }
    }
}

// ---------------- CSR build: scan + scatter ----------------
__global__ void scan_k1(int n) {
    __shared__ int sh[256];
    int base = blockIdx.x * SCHUNK;
    int s = 0;
    for (int i = threadIdx.x; i < SCHUNK; i += 256) {
        int g = base + i;
        s += (g < n) ? d_degi[g] : 0;
    }
    sh[threadIdx.x] = s;
    __syncthreads();
    for (int o = 128; o; o >>= 1) {
        if (threadIdx.x < o) sh[threadIdx.x] += sh[threadIdx.x + o];
        __syncthreads();
    }
    if (threadIdx.x == 0) d_part[blockIdx.x] = sh[0];
}

__global__ void scan_k2(int G) {
    if (threadIdx.x == 0) {
        int acc = 0;
        for (int i = 0; i < G; i++) { int v = d_part[i]; d_part[i] = acc; acc += v; }
    }
}

__global__ void scan_k3(int n) {
    __shared__ int sh[256];
    int tid = threadIdx.x;
    int base = blockIdx.x * SCHUNK + tid * 8;
    int v[8], dg[8];
    int run = 0;
    #pragma unroll
    for (int j = 0; j < 8; j++) {
        int g = base + j;
        dg[j] = (g < n) ? d_degi[g] : 0;
        v[j] = run;
        run += dg[j];
    }
    sh[tid] = run;
    __syncthreads();
    for (int o = 1; o < 256; o <<= 1) {
        int t = (tid >= o) ? sh[tid - o] : 0;
        __syncthreads();
        sh[tid] += t;
        __syncthreads();
    }
    int off = d_part[blockIdx.x] + sh[tid] - run;
    #pragma unroll
    for (int j = 0; j < 8; j++) {
        int g = base + j;
        if (g < n) {
            int r = off + v[j];
            d_rowptr[g] = r;
            d_fill[g]   = r;
            if (g == n - 1) d_rowptr[n] = r + dg[j];
        }
    }
}

__global__ void scatter_kernel(const void* edges, int E) {
    int e = blockIdx.x * blockDim.x + threadIdx.x;
    if (e >= E) return;
    int s, d;
    if (d_is64) {
        const long long* p = (const long long*)edges;
        s = (int)p[e]; d = (int)p[e + E];
    } else {
        const int* p = (const int*)edges;
        s = p[e]; d = p[e + E];
    }
    int pos = atomicAdd(&d_fill[d], 1);
    d_csri[pos] = s;
}

// ---------------- CSR aggregation, layer 1 — feature-half pass (L2 blocking) ----------------
// agg1[d][f] = dinv[d] * ( y1[d][f] + sum_{s in N(d)} y1[s][f] ) for f in [fo4*4, fo4*4+128)
// 32 threads/node, float4 lanes; two passes keep the 51MB half of y1 L2-resident.
__global__ __launch_bounds__(256) void csr_agg1_half(const float* __restrict__ y,
                                                     float* __restrict__ outp,
                                                     int n, int fo4) {
    int node = blockIdx.x * 8 + (threadIdx.x >> 5);
    int t = threadIdx.x & 31;
    if (node >= n) return;
    const float4* __restrict__ y4 = (const float4*)y;
    size_t base = (size_t)node * 64 + fo4 + t;
    float4 acc = y4[base];
    int e   = d_rowptr[node];
    int end = d_rowptr[node + 1];
    for (; e + 4 <= end; e += 4) {
        int s0 = d_csri[e], s1 = d_csri[e+1], s2 = d_csri[e+2], s3 = d_csri[e+3];
        float4 v0 = y4[(size_t)s0 * 64 + fo4 + t];
        float4 v1 = y4[(size_t)s1 * 64 + fo4 + t];
        float4 v2 = y4[(size_t)s2 * 64 + fo4 + t];
        float4 v3 = y4[(size_t)s3 * 64 + fo4 + t];
        acc.x += v0.x + v1.x + v2.x + v3.x;
        acc.y += v0.y + v1.y + v2.y + v3.y;
        acc.z += v0.z + v1.z + v2.z + v3.z;
        acc.w += v0.w + v1.w + v2.w + v3.w;
    }
    for (; e < end; e++) {
        float4 v = y4[(size_t)d_csri[e] * 64 + fo4 + t];
        acc.x += v.x; acc.y += v.y; acc.z += v.z; acc.w += v.w;
    }
    float dv = d_dinv[node];
    acc.x *= dv; acc.y *= dv; acc.z *= dv; acc.w *= dv;
    ((float4*)outp)[base] = acc;
}

// ---------------- SGEMM 2: y2 = dinv * (relu(agg1 + b1) @ W2), f32x2 ----------------
__global__ __launch_bounds__(256) void gemm2_kernel(const float* __restrict__ A,
                                                    const float* __restrict__ b1,
                                                    const float* __restrict__ B,
                                                    float* __restrict__ C, int n) {
    __shared__ float As[16][64];
    __shared__ float Bs[16][64];
    int tid = threadIdx.x;
    int tx = tid & 15, ty = tid >> 4;
    int row0 = blockIdx.x * 64;
    int aRow = tid >> 2, aCol = (tid & 3) << 2;
    int bRow = tid >> 4, bCol = (tid & 15) << 2;
    ull acc[4][2];
    #pragma unroll
    for (int i = 0; i < 4; i++) { acc[i][0] = 0ull; acc[i][1] = 0ull; }
    int gr = row0 + aRow;
    for (int k0 = 0; k0 < HIDD; k0 += 16) {
        float4 av = make_float4(0,0,0,0);
        if (gr < n) {
            av = *(const float4*)(A + (size_t)gr * HIDD + k0 + aCol);
            float4 bb = *(const float4*)(b1 + k0 + aCol);
            av.x = fmaxf(av.x + bb.x, 0.f);
            av.y = fmaxf(av.y + bb.y, 0.f);
            av.z = fmaxf(av.z + bb.z, 0.f);
            av.w = fmaxf(av.w + bb.w, 0.f);
        }
        float4 bv = *(const float4*)(B + (size_t)(k0 + bRow) * CCH + bCol);
        As[aCol+0][aRow]=av.x; As[aCol+1][aRow]=av.y; As[aCol+2][aRow]=av.z; As[aCol+3][aRow]=av.w;
        *(float4*)&Bs[bRow][bCol] = bv;
        __syncthreads();
        #pragma unroll
        for (int kk = 0; kk < 16; kk++) {
            float a[4];
            *(float4*)(a) = *(const float4*)&As[kk][ty<<2];
            ull b0 = *(const ull*)&Bs[kk][tx<<2];
            ull b1p = *(const ull*)&Bs[kk][(tx<<2) + 2];
            #pragma unroll
            for (int i = 0; i < 4; i++) {
                ull ai;
                PACK_DUP(ai, a[i]);
                FMA_F32X2(acc[i][0], ai, b0);
                FMA_F32X2(acc[i][1], ai, b1p);
            }
        }
        __syncthreads();
    }
    #pragma unroll
    for (int i = 0; i < 4; i++) {
        int r = row0 + (ty<<2) + i;
        if (r < n) {
            float dv = d_dinv[r];
            uint32_t lo, hi;
            float c0, c1v, c2v, c3v;
            UNPACK2(lo, hi, acc[i][0]); c0 = __uint_as_float(lo) * dv; c1v = __uint_as_float(hi) * dv;
            UNPACK2(lo, hi, acc[i][1]); c2v = __uint_as_float(lo) * dv; c3v = __uint_as_float(hi) * dv;
            *(float4*)(C + (size_t)r * CCH + (tx<<2)) = make_float4(c0, c1v, c2v, c3v);
        }
    }
}

// ---------------- CSR aggregation layer 2 fused with x1 = agg+b2 and score ----------------
__global__ __launch_bounds__(256) void csr_agg2(const float* __restrict__ y,
                                                const float* __restrict__ b2,
                                                const float* __restrict__ Wp,
                                                const float* __restrict__ bp, int n) {
    int node = blockIdx.x * 16 + (threadIdx.x >> 4);
    int t = threadIdx.x & 15;
    if (node >= n) return;
    const float4* __restrict__ y4 = (const float4*)y;
    float4 acc = y4[(size_t)node * 16 + t];
    int e   = d_rowptr[node];
    int end = d_rowptr[node + 1];
    for (; e + 4 <= end; e += 4) {
        int s0 = d_csri[e], s1 = d_csri[e+1], s2 = d_csri[e+2], s3 = d_csri[e+3];
        float4 v0 = y4[(size_t)s0 * 16 + t];
        float4 v1 = y4[(size_t)s1 * 16 + t];
        float4 v2 = y4[(size_t)s2 * 16 + t];
        float4 v3 = y4[(size_t)s3 * 16 + t];
        acc.x += v0.x + v1.x + v2.x + v3.x;
        acc.y += v0.y + v1.y + v2.y + v3.y;
        acc.z += v0.z + v1.z + v2.z + v3.z;
        acc.w += v0.w + v1.w + v2.w + v3.w;
    }
    for (; e < end; e++) {
        float4 v = y4[(size_t)d_csri[e] * 16 + t];
        acc.x += v.x; acc.y += v.y; acc.z += v.z; acc.w += v.w;
    }
    float dv = d_dinv[node];
    float4 bb = ((const float4*)b2)[t];
    acc.x = acc.x * dv + bb.x;
    acc.y = acc.y * dv + bb.y;
    acc.z = acc.z * dv + bb.z;
    acc.w = acc.w * dv + bb.w;
    ((float4*)d_x1)[(size_t)node * 16 + t] = acc;
    float4 wp = ((const float4*)Wp)[t];
    float p = acc.x*wp.x + acc.y*wp.y + acc.z*wp.z + acc.w*wp.w;
    unsigned gm = 0xFFFFu << (threadIdx.x & 16);
    #pragma unroll
    for (int o = 8; o; o >>= 1) p += __shfl_xor_sync(gm, p, o);
    if (t == 0) d_score[node] = p + bp[0];
}

// ---------------- bitonic argsort ----------------
// local sort with fused fill (keys from d_score, padded with +inf)
__global__ __launch_bounds__(1024) void bitonic_local_sort_fill(int n) {
    __shared__ float sk[2048];
    __shared__ int   sv[2048];
    int base = blockIdx.x * 2048;
    int tid = threadIdx.x;
    int g0 = base + tid, g1 = base + tid + 1024;
    sk[tid]        = (g0 < n) ? d_score[g0] : 3.0e38f;  sv[tid]        = g0;
    sk[tid + 1024] = (g1 < n) ? d_score[g1] : 3.0e38f;  sv[tid + 1024] = g1;
    for (int k = 2; k <= 2048; k <<= 1) {
        for (int j = k >> 1; j > 0; j >>= 1) {
            __syncthreads();
            int i = ((tid & ~(j - 1)) << 1) | (tid & (j - 1));
            int p = i | j;
            bool up = (((base + i) & k) == 0);
            float a = sk[i], b = sk[p];
            if ((a > b) == up) {
                sk[i] = b; sk[p] = a;
                int t = sv[i]; sv[i] = sv[p]; sv[p] = t;
            }
        }
    }
    __syncthreads();
    d_keys[base + tid]        = sk[tid];        d_vals[base + tid]        = sv[tid];
    d_keys[base + tid + 1024] = sk[tid + 1024]; d_vals[base + tid + 1024] = sv[tid + 1024];
}

// Fused strided steps (coalesced mapping)
__global__ __launch_bounds__(1024) void bitonic_strided(int kp) {
    __shared__ float sk[32 * 66];
    __shared__ int   sv[32 * 66];
    int tid = threadIdx.x;
    int low0 = blockIdx.x * 32;
    for (int i = tid; i < 2048; i += 1024) {
        int li = i & 31, t = i >> 5;
        int idx = (low0 + li) + (t << 11);
        sk[li * 66 + t] = d_keys[idx];
        sv[li * 66 + t] = d_vals[idx];
    }
    for (int jp = kp >> 1; jp > 0; jp >>= 1) {
        __syncthreads();
        int li = tid >> 5, q = tid & 31;
        int ti = ((q & ~(jp - 1)) << 1) | (q & (jp - 1));
        int tp = ti | jp;
        bool up = ((ti & kp) == 0);
        float a = sk[li * 66 + ti], b = sk[li * 66 + tp];
        if ((a > b) == up) {
            sk[li * 66 + ti] = b; sk[li * 66 + tp] = a;
            int tv = sv[li * 66 + ti]; sv[li * 66 + ti] = sv[li * 66 + tp]; sv[li * 66 + tp] = tv;
        }
    }
    __syncthreads();
    for (int i = tid; i < 2048; i += 1024) {
        int li = i & 31, t = i >> 5;
        int idx = (low0 + li) + (t << 11);
        d_keys[idx] = sk[li * 66 + t];
        d_vals[idx] = sv[li * 66 + t];
    }
}

__global__ __launch_bounds__(1024) void bitonic_local_merge(int K) {
    __shared__ float sk[2048];
    __shared__ int   sv[2048];
    int base = blockIdx.x * 2048;
    int tid = threadIdx.x;
    sk[tid]        = d_keys[base + tid];        sv[tid]        = d_vals[base + tid];
    sk[tid + 1024] = d_keys[base + tid + 1024]; sv[tid + 1024] = d_vals[base + tid + 1024];
    for (int j = 1024; j > 0; j >>= 1) {
        __syncthreads();
        int i = ((tid & ~(j - 1)) << 1) | (tid & (j - 1));
        int p = i | j;
        bool up = (((base + i) & K) == 0);
        float a = sk[i], b = sk[p];
        if ((a > b) == up) {
            sk[i] = b; sk[p] = a;
            int t = sv[i]; sv[i] = sv[p]; sv[p] = t;
        }
    }
    __syncthreads();
    d_keys[base + tid]        = sk[tid];        d_vals[base + tid]        = sv[tid];
    d_keys[base + tid + 1024] = sk[tid + 1024]; d_vals[base + tid + 1024] = sv[tid + 1024];
}

__global__ void inverse_kernel(int n) {
    int r = blockIdx.x * blockDim.x + threadIdx.x;
    if (r < n) d_invp[d_vals[r]] = r;
}

// ---------------- conv1d (C=64, K=5, SAME); variant 1 fuses sorted-x gather ----------------
__global__ __launch_bounds__(1024) void conv_gather_kernel(const float* __restrict__ w,
                                                           const float* __restrict__ b,
                                                           float* __restrict__ outp, int n) {
    __shared__ float xs[68][64];
    __shared__ float ws[64][84];   // 16B-aligned rows so ptxas can vectorize LDS
    int tid = threadIdx.x;
    int l0 = blockIdx.x * 64;
    for (int i = tid; i < 68 * 64; i += 1024) {
        int r = i >> 6, c = i & 63;
        int g = l0 - 2 + r;
        float v = 0.f;
        if (g >= 0 && g < n)
            v = d_keys[g] * d_x1[(size_t)d_vals[g] * 64 + c];
        xs[r][c] = v;
    }
    int co = tid & 63;
    int grp = tid >> 6;
    int pb = grp << 2;
    float a0 = 0.f, a1 = 0.f, a2 = 0.f, a3 = 0.f;
    for (int cc = 0; cc < 64; cc += 16) {
        __syncthreads();
        for (int i = tid; i < 64 * 80; i += 1024) {
            int wco = i / 80;
            int rem = i - wco * 80;
            ws[wco][rem] = w[((size_t)wco * 64 + cc + rem / 5) * 5 + (rem % 5)];
        }
        __syncthreads();
        #pragma unroll
        for (int ci = 0; ci < 16; ci++) {
            float x0 = xs[pb+0][cc+ci], x1 = xs[pb+1][cc+ci], x2 = xs[pb+2][cc+ci],
                  x3 = xs[pb+3][cc+ci], x4 = xs[pb+4][cc+ci], x5 = xs[pb+5][cc+ci],
                  x6 = xs[pb+6][cc+ci], x7 = xs[pb+7][cc+ci];
            float w0 = ws[co][ci*5+0], w1 = ws[co][ci*5+1], w2 = ws[co][ci*5+2],
                  w3 = ws[co][ci*5+3], w4 = ws[co][ci*5+4];
            a0 += x0*w0 + x1*w1 + x2*w2 + x3*w3 + x4*w4;
            a1 += x1*w0 + x2*w1 + x3*w2 + x4*w3 + x5*w4;
            a2 += x2*w0 + x3*w1 + x4*w2 + x5*w3 + x6*w4;
            a3 += x3*w0 + x4*w1 + x5*w2 + x6*w3 + x7*w4;
        }
    }
    float bb = b[co];
    int gl = l0 + pb;
    float r0 = fmaxf(a0 + bb, 0.f), r1 = fmaxf(a1 + bb, 0.f);
    float r2 = fmaxf(a2 + bb, 0.f), r3 = fmaxf(a3 + bb, 0.f);
    if (gl + 0 < n) outp[(size_t)(gl+0)*64 + co] = r0;
    if (gl + 1 < n) outp[(size_t)(gl+1)*64 + co] = r1;
    if (gl + 2 < n) outp[(size_t)(gl+2)*64 + co] = r2;
    if (gl + 3 < n) outp[(size_t)(gl+3)*64 + co] = r3;
}

__global__ __launch_bounds__(1024) void conv_kernel(const float* __restrict__ xin,
                                                    const float* __restrict__ w,
                                                    const float* __restrict__ b,
                                                    float* __restrict__ outp, int n) {
    __shared__ float xs[68][64];
    __shared__ float ws[64][84];
    int tid = threadIdx.x;
    int l0 = blockIdx.x * 64;
    for (int i = tid; i < 68 * 64; i += 1024) {
        int r = i >> 6, c = i & 63;
        int g = l0 - 2 + r;
        xs[r][c] = (g >= 0 && g < n) ? xin[(size_t)g * 64 + c] : 0.f;
    }
    int co = tid & 63;
    int grp = tid >> 6;
    int pb = grp << 2;
    float a0 = 0.f, a1 = 0.f, a2 = 0.f, a3 = 0.f;
    for (int cc = 0; cc < 64; cc += 16) {
        __syncthreads();
        for (int i = tid; i < 64 * 80; i += 1024) {
            int wco = i / 80;
            int rem = i - wco * 80;
            ws[wco][rem] = w[((size_t)wco * 64 + cc + rem / 5) * 5 + (rem % 5)];
        }
        __syncthreads();
        #pragma unroll
        for (int ci = 0; ci < 16; ci++) {
            float x0 = xs[pb+0][cc+ci], x1 = xs[pb+1][cc+ci], x2 = xs[pb+2][cc+ci],
                  x3 = xs[pb+3][cc+ci], x4 = xs[pb+4][cc+ci], x5 = xs[pb+5][cc+ci],
                  x6 = xs[pb+6][cc+ci], x7 = xs[pb+7][cc+ci];
            float w0 = ws[co][ci*5+0], w1 = ws[co][ci*5+1], w2 = ws[co][ci*5+2],
                  w3 = ws[co][ci*5+3], w4 = ws[co][ci*5+4];
            a0 += x0*w0 + x1*w1 + x2*w2 + x3*w3 + x4*w4;
            a1 += x1*w0 + x2*w1 + x3*w2 + x4*w3 + x5*w4;
            a2 += x2*w0 + x3*w1 + x4*w2 + x5*w3 + x6*w4;
            a3 += x3*w0 + x4*w1 + x5*w2 + x6*w3 + x7*w4;
        }
    }
    float bb = b[co];
    int gl = l0 + pb;
    float r0 = a0 + bb, r1 = a1 + bb, r2 = a2 + bb, r3 = a3 + bb;
    if (gl + 0 < n) outp[(size_t)(gl+0)*64 + co] = r0;
    if (gl + 1 < n) outp[(size_t)(gl+1)*64 + co] = r1;
    if (gl + 2 < n) outp[(size_t)(gl+2)*64 + co] = r2;
    if (gl + 3 < n) outp[(size_t)(gl+3)*64 + co] = r3;
}

// ---------------- final: out = log_softmax([x1, x2] @ Wl + bl) ----------------
__global__ __launch_bounds__(256) void gemm3_kernel(const float* __restrict__ Wl,
                                                    const float* __restrict__ bl,
                                                    float* __restrict__ outp, int n) {
    __shared__ float As[16][64];
    __shared__ float Bs[16][64];
    __shared__ float Cs[64][65];
    int tid = threadIdx.x;
    int tx = tid & 15, ty = tid >> 4;
    int row0 = blockIdx.x * 64;
    int aRow = tid >> 2, aCol = (tid & 3) << 2;
    int bRow = tid >> 4, bCol = (tid & 15) << 2;
    ull acc[4][2];
    #pragma unroll
    for (int i = 0; i < 4; i++) { acc[i][0] = 0ull; acc[i][1] = 0ull; }
    int gr = row0 + aRow;
    int inv = (gr < n) ? d_invp[gr] : 0;
    for (int k0 = 0; k0 < 128; k0 += 16) {
        int kg = k0 + aCol;
        float4 av = make_float4(0,0,0,0);
        if (gr < n) {
            if (kg < 64) av = *(const float4*)(d_x1 + (size_t)gr * 64 + kg);
            else         av = *(const float4*)(d_c2 + (size_t)inv * 64 + (kg - 64));
        }
        float4 bv = *(const float4*)(Wl + (size_t)(k0 + bRow) * 64 + bCol);
        As[aCol+0][aRow]=av.x; As[aCol+1][aRow]=av.y; As[aCol+2][aRow]=av.z; As[aCol+3][aRow]=av.w;
        *(float4*)&Bs[bRow][bCol] = bv;
        __syncthreads();
        #pragma unroll
        for (int kk = 0; kk < 16; kk++) {
            float a[4];
            *(float4*)(a) = *(const float4*)&As[kk][ty<<2];
            ull b0 = *(const ull*)&Bs[kk][tx<<2];
            ull b1p = *(const ull*)&Bs[kk][(tx<<2) + 2];
            #pragma unroll
            for (int i = 0; i < 4; i++) {
                ull ai;
                PACK_DUP(ai, a[i]);
                FMA_F32X2(acc[i][0], ai, b0);
                FMA_F32X2(acc[i][1], ai, b1p);
            }
        }
        __syncthreads();
    }
    #pragma unroll
    for (int i = 0; i < 4; i++) {
        uint32_t lo, hi;
        float c0, c1v, c2v, c3v;
        UNPACK2(lo, hi, acc[i][0]); c0 = __uint_as_float(lo); c1v = __uint_as_float(hi);
        UNPACK2(lo, hi, acc[i][1]); c2v = __uint_as_float(lo); c3v = __uint_as_float(hi);
        int cb = tx << 2;
        Cs[(ty<<2)+i][cb+0] = c0  + bl[cb+0];
        Cs[(ty<<2)+i][cb+1] = c1v + bl[cb+1];
        Cs[(ty<<2)+i][cb+2] = c2v + bl[cb+2];
        Cs[(ty<<2)+i][cb+3] = c3v + bl[cb+3];
    }
    __syncthreads();
    if (tid < 64) {
        int grow = row0 + tid;
        if (grow < n) {
            float m = -3.0e38f;
            #pragma unroll
            for (int c = 0; c < 64; c++) m = fmaxf(m, Cs[tid][c]);
            float s = 0.f;
            #pragma unroll
            for (int c = 0; c < 64; c++) s += expf(Cs[tid][c] - m);
            float lse = m + logf(s);
            for (int c = 0; c < 64; c++)
                outp[(size_t)grow * 64 + c] = Cs[tid][c] - lse;
        }
    }
}

// ---------------- host launcher ----------------
extern "C" void kernel_launch(void* const* d_in, const int* in_sizes, int n_in,
                              void* d_out, int out_size) {
    const float* x   = (const float*)d_in[0];
    const void*  edg = d_in[1];
    const float* W1  = (const float*)d_in[2];
    const float* b1  = (const float*)d_in[3];
    const float* W2  = (const float*)d_in[4];
    const float* b2  = (const float*)d_in[5];
    const float* Wp  = (const float*)d_in[6];
    const float* bp  = (const float*)d_in[7];
    const float* cw1 = (const float*)d_in[8];
    const float* cb1 = (const float*)d_in[9];
    const float* cw2 = (const float*)d_in[10];
    const float* cb2 = (const float*)d_in[11];
    const float* Wl  = (const float*)d_in[12];
    const float* bl  = (const float*)d_in[13];
    float* out = (float*)d_out;

    int n = in_sizes[0] / FIN;
    int E = in_sizes[1] / 2;
    int G = (n + SCHUNK - 1) / SCHUNK;

    float *p_hw1, *p_agg1, *p_hw2, *p_c1, *p_c2;
    cudaGetSymbolAddress((void**)&p_hw1,  d_hw1);
    cudaGetSymbolAddress((void**)&p_agg1, d_agg1);
    cudaGetSymbolAddress((void**)&p_hw2,  d_hw2);
    cudaGetSymbolAddress((void**)&p_c1,   d_c1);
    cudaGetSymbolAddress((void**)&p_c2,   d_c2);

    // 0-3: edge prep (detect is a 1-warp sniff; zero_deg is grid-wide)
    detect_kernel<<<1, 32>>>(edg, (long long)E, n);                // 0
    zero_deg<<<(n + 255) / 256, 256>>>(n);                         // 1
    count_deg<<<(E + 255) / 256, 256>>>(edg, E);                   // 2
    compute_dinv<<<(n + 255) / 256, 256>>>(n);                     // 3

    // 4: gemm1 — still early so ncu window covers it if offsets shift
    gemm1_kernel<<<dim3((n + 63) / 64, HIDD / 64), 128>>>(x, W1, p_hw1, n);  // 4

    // CSR build
    scan_k1<<<G, 256>>>(n);
    scan_k2<<<1, 32>>>(G);
    scan_k3<<<G, 256>>>(n);
    scatter_kernel<<<(E + 255) / 256, 256>>>(edg, E);

    // GCN layer 1 aggregation — two feature-half passes (L2 blocking)
    csr_agg1_half<<<(n + 7) / 8, 256>>>(p_hw1, p_agg1, n, 0);
    csr_agg1_half<<<(n + 7) / 8, 256>>>(p_hw1, p_agg1, n, 32);

    // GCN layer 2 (bias+relu fused into A-load; dinv folded into epilogue)
    gemm2_kernel<<<(n + 63) / 64, 256>>>(p_agg1, b1, W2, p_hw2, n);
    csr_agg2<<<(n + 15) / 16, 256>>>(p_hw2, b2, Wp, bp, n);

    // argsort (fill fused into local sort)
    bitonic_local_sort_fill<<<MSORT / 2048, 1024>>>(n);
    for (int k = 4096; k <= MSORT; k <<= 1) {
        bitonic_strided<<<MSORT / 2048, 1024>>>(k >> 11);
        bitonic_local_merge<<<MSORT / 2048, 1024>>>(k);
    }
    inverse_kernel<<<(n + 255) / 256, 256>>>(n);

    // conv1d x2 (conv1 fuses sorted-x gather+scale)
    conv_gather_kernel<<<(n + 63) / 64, 1024>>>(cw1, cb1, p_c1, n);
    conv_kernel<<<(n + 63) / 64, 1024>>>(p_c1, cw2, cb2, p_c2, n);

    // final linear + log_softmax
    gemm3_kernel<<<(n + 63) / 64, 256>>>(Wl, bl, out, n);
}

// round 16
// speedup vs baseline: 1.5381x; 1.5381x over previous
#include <cuda_runtime.h>
#include <cuda_bf16.h>
#include <math.h>
#include <stdint.h>

#define NN    100000
#define FIN   512
#define HIDD  256
#define CCH   64
#define EMAX  3300000
#define MSORT 131072
#define SCHUNK 2048

typedef unsigned long long ull;

// packed fp32x2 FMA (Blackwell family-wide PTX; SASS FFMA2)
#define FMA_F32X2(d, a, b) \
    asm("fma.rn.f32x2 %0, %1, %2, %3;" : "=l"(d) : "l"(a), "l"(b), "l"(d))
#define PACK_DUP(out, v) \
    asm("mov.b64 %0, {%1, %1};" : "=l"(out) : "r"(__float_as_uint(v)))
#define PACK2(out, a, b) \
    asm("mov.b64 %0, {%1, %2};" : "=l"(out) : "r"(__float_as_uint(a)), "r"(__float_as_uint(b)))
#define UNPACK2(lo, hi, in) \
    asm("mov.b64 {%0, %1}, %2;" : "=r"(lo), "=r"(hi) : "l"(in))

// ---------------- scratch (device globals; no allocation) ----------------
__device__ float d_hw1 [(size_t)NN * HIDD];   // y1 = dinv[r] * (x@W1)[r]
__device__ float d_agg1[(size_t)NN * HIDD];
__device__ float d_hw2 [(size_t)NN * CCH];    // y2 = dinv[r] * (relu(agg1+b1)@W2)[r]
__device__ float d_x1  [(size_t)NN * CCH];
__device__ float d_score[NN];
__device__ int   d_degi[NN];
__device__ float d_dinv[NN];
__device__ int   d_rowptr[NN + 1];
__device__ int   d_fill[NN];
__device__ int   d_part[256];
__device__ int   d_csri[EMAX];         // src index only
__device__ float d_keys[MSORT];
__device__ int   d_vals[MSORT];
__device__ int   d_invp[NN];
__device__ float d_c1  [(size_t)NN * CCH];
__device__ float d_c2  [(size_t)NN * CCH];
__device__ int   d_is64;

// ---------------- edge dtype detect + zero degrees ----------------
__global__ void detect_kernel(const void* edges, long long nElemsI64, int n) {
    for (int i = threadIdx.x; i < n; i += blockDim.x) d_degi[i] = 0;
    if (threadIdx.x == 0) {
        const long long* p = (const long long*)edges;
        int cnt = (int)(nElemsI64 < 256 ? nElemsI64 : 256);
        int ok = 1;
        for (int i = 0; i < cnt; i++) {
            long long v = p[i];
            if (v < 0 || v >= (long long)n) { ok = 0; break; }
        }
        d_is64 = ok;
    }
}

__global__ void count_deg(const void* edges, int E) {
    int e = blockIdx.x * blockDim.x + threadIdx.x;
    if (e >= E) return;
    int d;
    if (d_is64) d = (int)((const long long*)edges)[e + E];
    else        d = ((const int*)edges)[e + E];
    atomicAdd(&d_degi[d], 1);
}

__global__ void compute_dinv(int n) {
    int i = blockIdx.x * blockDim.x + threadIdx.x;
    if (i < n) d_dinv[i] = rsqrtf((float)(d_degi[i] + 1));
}

// ---------------- SGEMM 1: y1 = dinv * (x @ W1)   64x64 tile, 128 thr ----------------
__global__ __launch_bounds__(128) void gemm1_kernel(const float* __restrict__ A,
                                                    const float* __restrict__ B,
                                                    float* __restrict__ C, int n) {
    __shared__ float As[8][68];
    __shared__ float Bs[8][68];
    int tid = threadIdx.x;
    int row0 = blockIdx.x * 64;
    int col0 = blockIdx.y * 64;
    int aRow = tid >> 1;            // 0..63
    int aK   = (tid & 1) << 2;      // 0 or 4
    int bK   = tid >> 4;            // 0..7
    int bCol = (tid & 15) << 2;     // 0..60
    int ty = tid >> 4;              // 0..7
    int tx = tid & 15;              // 0..15
    int cr4 = ty << 2;              // rows cr4..+3 and +32
    int cc4 = tx << 2;              // cols cc4..+3
    ull acc[8][2];
    #pragma unroll
    for (int i = 0; i < 8; i++) { acc[i][0] = 0ull; acc[i][1] = 0ull; }
    int gr = row0 + aRow;
    for (int k0 = 0; k0 < FIN; k0 += 8) {
        float4 av = make_float4(0,0,0,0);
        if (gr < n) av = *(const float4*)(A + (size_t)gr * FIN + k0 + aK);
        float4 bv = *(const float4*)(B + (size_t)(k0 + bK) * HIDD + col0 + bCol);
        As[aK+0][aRow] = av.x; As[aK+1][aRow] = av.y;
        As[aK+2][aRow] = av.z; As[aK+3][aRow] = av.w;
        *(float4*)&Bs[bK][bCol] = bv;
        __syncthreads();
        #pragma unroll
        for (int kk = 0; kk < 8; kk++) {
            float a[8];
            *(float4*)(a)     = *(const float4*)&As[kk][cr4];
            *(float4*)(a + 4) = *(const float4*)&As[kk][cr4 + 32];
            float4 bq = *(const float4*)&Bs[kk][cc4];
            ull b0, b1;
            PACK2(b0, bq.x, bq.y);
            PACK2(b1, bq.z, bq.w);
            #pragma unroll
            for (int i = 0; i < 8; i++) {
                ull ai;
                PACK_DUP(ai, a[i]);
                FMA_F32X2(acc[i][0], ai, b0);
                FMA_F32X2(acc[i][1], ai, b1);
            }
        }
        __syncthreads();
    }
    #pragma unroll
    for (int i = 0; i < 8; i++) {
        int r = row0 + cr4 + (i & 3) + ((i >> 2) << 5);   // +0 or +32
        if (r < n) {
            float dv = d_dinv[r];
            uint32_t lo, hi;
            float c0, c1v, c2v, c3v;
            UNPACK2(lo, hi, acc[i][0]); c0  = __uint_as_float(lo) * dv; c1v = __uint_as_float(hi) * dv;
            UNPACK2(lo, hi, acc[i][1]); c2v = __uint_as_float(lo) * dv; c3v = __uint_as_float(hi) * dv;
            *(float4*)(C + (size_t)r * HIDD + col0 + cc4) = make_float4(c0, c1v, c2v, c3v);
        }
    }
}

// ---------------- CSR build: scan + scatter ----------------
__global__ void scan_k1(int n) {
    __shared__ int sh[256];
    int base = blockIdx.x * SCHUNK;
    int s = 0;
    for (int i = threadIdx.x; i < SCHUNK; i += 256) {
        int g = base + i;
        s += (g < n) ? d_degi[g] : 0;
    }
    sh[threadIdx.x] = s;
    __syncthreads();
    for (int o = 128; o; o >>= 1) {
        if (threadIdx.x < o) sh[threadIdx.x] += sh[threadIdx.x + o];
        __syncthreads();
    }
    if (threadIdx.x == 0) d_part[blockIdx.x] = sh[0];
}

__global__ void scan_k2(int G) {
    if (threadIdx.x == 0) {
        int acc = 0;
        for (int i = 0; i < G; i++) { int v = d_part[i]; d_part[i] = acc; acc += v; }
    }
}

__global__ void scan_k3(int n) {
    __shared__ int sh[256];
    int tid = threadIdx.x;
    int base = blockIdx.x * SCHUNK + tid * 8;
    int v[8], dg[8];
    int run = 0;
    #pragma unroll
    for (int j = 0; j < 8; j++) {
        int g = base + j;
        dg[j] = (g < n) ? d_degi[g] : 0;
        v[j] = run;
        run += dg[j];
    }
    sh[tid] = run;
    __syncthreads();
    for (int o = 1; o < 256; o <<= 1) {
        int t = (tid >= o) ? sh[tid - o] : 0;
        __syncthreads();
        sh[tid] += t;
        __syncthreads();
    }
    int off = d_part[blockIdx.x] + sh[tid] - run;
    #pragma unroll
    for (int j = 0; j < 8; j++) {
        int g = base + j;
        if (g < n) {
            int r = off + v[j];
            d_rowptr[g] = r;
            d_fill[g]   = r;
            if (g == n - 1) d_rowptr[n] = r + dg[j];
        }
    }
}

__global__ void scatter_kernel(const void* edges, int E) {
    int e = blockIdx.x * blockDim.x + threadIdx.x;
    if (e >= E) return;
    int s, d;
    if (d_is64) {
        const long long* p = (const long long*)edges;
        s = (int)p[e]; d = (int)p[e + E];
    } else {
        const int* p = (const int*)edges;
        s = p[e]; d = p[e + E];
    }
    int pos = atomicAdd(&d_fill[d], 1);
    d_csri[pos] = s;
}

// ---------------- CSR aggregation, layer 1 — feature-half pass (L2 blocking) ----------------
__global__ __launch_bounds__(256) void csr_agg1_half(const float* __restrict__ y,
                                                     float* __restrict__ outp,
                                                     int n, int fo4) {
    int node = blockIdx.x * 8 + (threadIdx.x >> 5);
    int t = threadIdx.x & 31;
    if (node >= n) return;
    const float4* __restrict__ y4 = (const float4*)y;
    size_t base = (size_t)node * 64 + fo4 + t;
    float4 acc = y4[base];
    int e   = d_rowptr[node];
    int end = d_rowptr[node + 1];
    for (; e + 4 <= end; e += 4) {
        int s0 = d_csri[e], s1 = d_csri[e+1], s2 = d_csri[e+2], s3 = d_csri[e+3];
        float4 v0 = y4[(size_t)s0 * 64 + fo4 + t];
        float4 v1 = y4[(size_t)s1 * 64 + fo4 + t];
        float4 v2 = y4[(size_t)s2 * 64 + fo4 + t];
        float4 v3 = y4[(size_t)s3 * 64 + fo4 + t];
        acc.x += v0.x + v1.x + v2.x + v3.x;
        acc.y += v0.y + v1.y + v2.y + v3.y;
        acc.z += v0.z + v1.z + v2.z + v3.z;
        acc.w += v0.w + v1.w + v2.w + v3.w;
    }
    for (; e < end; e++) {
        float4 v = y4[(size_t)d_csri[e] * 64 + fo4 + t];
        acc.x += v.x; acc.y += v.y; acc.z += v.z; acc.w += v.w;
    }
    float dv = d_dinv[node];
    acc.x *= dv; acc.y *= dv; acc.z *= dv; acc.w *= dv;
    ((float4*)outp)[base] = acc;
}

// ---------------- SGEMM 2: y2 = dinv * (relu(agg1 + b1) @ W2), f32x2 ----------------
__global__ __launch_bounds__(256) void gemm2_kernel(const float* __restrict__ A,
                                                    const float* __restrict__ b1,
                                                    const float* __restrict__ B,
                                                    float* __restrict__ C, int n) {
    __shared__ float As[16][64];
    __shared__ float Bs[16][64];
    int tid = threadIdx.x;
    int tx = tid & 15, ty = tid >> 4;
    int row0 = blockIdx.x * 64;
    int aRow = tid >> 2, aCol = (tid & 3) << 2;
    int bRow = tid >> 4, bCol = (tid & 15) << 2;
    ull acc[4][2];
    #pragma unroll
    for (int i = 0; i < 4; i++) { acc[i][0] = 0ull; acc[i][1] = 0ull; }
    int gr = row0 + aRow;
    for (int k0 = 0; k0 < HIDD; k0 += 16) {
        float4 av = make_float4(0,0,0,0);
        if (gr < n) {
            av = *(const float4*)(A + (size_t)gr * HIDD + k0 + aCol);
            float4 bb = *(const float4*)(b1 + k0 + aCol);
            av.x = fmaxf(av.x + bb.x, 0.f);
            av.y = fmaxf(av.y + bb.y, 0.f);
            av.z = fmaxf(av.z + bb.z, 0.f);
            av.w = fmaxf(av.w + bb.w, 0.f);
        }
        float4 bv = *(const float4*)(B + (size_t)(k0 + bRow) * CCH + bCol);
        As[aCol+0][aRow]=av.x; As[aCol+1][aRow]=av.y; As[aCol+2][aRow]=av.z; As[aCol+3][aRow]=av.w;
        *(float4*)&Bs[bRow][bCol] = bv;
        __syncthreads();
        #pragma unroll
        for (int kk = 0; kk < 16; kk++) {
            float a[4];
            *(float4*)(a) = *(const float4*)&As[kk][ty<<2];
            ull b0 = *(const ull*)&Bs[kk][tx<<2];
            ull b1p = *(const ull*)&Bs[kk][(tx<<2) + 2];
            #pragma unroll
            for (int i = 0; i < 4; i++) {
                ull ai;
                PACK_DUP(ai, a[i]);
                FMA_F32X2(acc[i][0], ai, b0);
                FMA_F32X2(acc[i][1], ai, b1p);
            }
        }
        __syncthreads();
    }
    #pragma unroll
    for (int i = 0; i < 4; i++) {
        int r = row0 + (ty<<2) + i;
        if (r < n) {
            float dv = d_dinv[r];
            uint32_t lo, hi;
            float c0, c1v, c2v, c3v;
            UNPACK2(lo, hi, acc[i][0]); c0 = __uint_as_float(lo) * dv; c1v = __uint_as_float(hi) * dv;
            UNPACK2(lo, hi, acc[i][1]); c2v = __uint_as_float(lo) * dv; c3v = __uint_as_float(hi) * dv;
            *(float4*)(C + (size_t)r * CCH + (tx<<2)) = make_float4(c0, c1v, c2v, c3v);
        }
    }
}

// ---------------- CSR aggregation layer 2 fused with x1 = agg+b2 and score ----------------
__global__ __launch_bounds__(256) void csr_agg2(const float* __restrict__ y,
                                                const float* __restrict__ b2,
                                                const float* __restrict__ Wp,
                                                const float* __restrict__ bp, int n) {
    int node = blockIdx.x * 16 + (threadIdx.x >> 4);
    int t = threadIdx.x & 15;
    if (node >= n) return;
    const float4* __restrict__ y4 = (const float4*)y;
    float4 acc = y4[(size_t)node * 16 + t];
    int e   = d_rowptr[node];
    int end = d_rowptr[node + 1];
    for (; e + 4 <= end; e += 4) {
        int s0 = d_csri[e], s1 = d_csri[e+1], s2 = d_csri[e+2], s3 = d_csri[e+3];
        float4 v0 = y4[(size_t)s0 * 16 + t];
        float4 v1 = y4[(size_t)s1 * 16 + t];
        float4 v2 = y4[(size_t)s2 * 16 + t];
        float4 v3 = y4[(size_t)s3 * 16 + t];
        acc.x += v0.x + v1.x + v2.x + v3.x;
        acc.y += v0.y + v1.y + v2.y + v3.y;
        acc.z += v0.z + v1.z + v2.z + v3.z;
        acc.w += v0.w + v1.w + v2.w + v3.w;
    }
    for (; e < end; e++) {
        float4 v = y4[(size_t)d_csri[e] * 16 + t];
        acc.x += v.x; acc.y += v.y; acc.z += v.z; acc.w += v.w;
    }
    float dv = d_dinv[node];
    float4 bb = ((const float4*)b2)[t];
    acc.x = acc.x * dv + bb.x;
    acc.y = acc.y * dv + bb.y;
    acc.z = acc.z * dv + bb.z;
    acc.w = acc.w * dv + bb.w;
    ((float4*)d_x1)[(size_t)node * 16 + t] = acc;
    float4 wp = ((const float4*)Wp)[t];
    float p = acc.x*wp.x + acc.y*wp.y + acc.z*wp.z + acc.w*wp.w;
    unsigned gm = 0xFFFFu << (threadIdx.x & 16);
    #pragma unroll
    for (int o = 8; o; o >>= 1) p += __shfl_xor_sync(gm, p, o);
    if (t == 0) d_score[node] = p + bp[0];
}

// ---------------- bitonic argsort ----------------
// local sort with fused fill (keys from d_score, padded with +inf)
__global__ __launch_bounds__(1024) void bitonic_local_sort_fill(int n) {
    __shared__ float sk[2048];
    __shared__ int   sv[2048];
    int base = blockIdx.x * 2048;
    int tid = threadIdx.x;
    int g0 = base + tid, g1 = base + tid + 1024;
    sk[tid]        = (g0 < n) ? d_score[g0] : 3.0e38f;  sv[tid]        = g0;
    sk[tid + 1024] = (g1 < n) ? d_score[g1] : 3.0e38f;  sv[tid + 1024] = g1;
    for (int k = 2; k <= 2048; k <<= 1) {
        for (int j = k >> 1; j > 0; j >>= 1) {
            __syncthreads();
            int i = ((tid & ~(j - 1)) << 1) | (tid & (j - 1));
            int p = i | j;
            bool up = (((base + i) & k) == 0);
            float a = sk[i], b = sk[p];
            if ((a > b) == up) {
                sk[i] = b; sk[p] = a;
                int t = sv[i]; sv[i] = sv[p]; sv[p] = t;
            }
        }
    }
    __syncthreads();
    d_keys[base + tid]        = sk[tid];        d_vals[base + tid]        = sv[tid];
    d_keys[base + tid + 1024] = sk[tid + 1024]; d_vals[base + tid + 1024] = sv[tid + 1024];
}

// Fused strided steps (coalesced mapping)
__global__ __launch_bounds__(1024) void bitonic_strided(int kp) {
    __shared__ float sk[32 * 66];
    __shared__ int   sv[32 * 66];
    int tid = threadIdx.x;
    int low0 = blockIdx.x * 32;
    for (int i = tid; i < 2048; i += 1024) {
        int li = i & 31, t = i >> 5;
        int idx = (low0 + li) + (t << 11);
        sk[li * 66 + t] = d_keys[idx];
        sv[li * 66 + t] = d_vals[idx];
    }
    for (int jp = kp >> 1; jp > 0; jp >>= 1) {
        __syncthreads();
        int li = tid >> 5, q = tid & 31;
        int ti = ((q & ~(jp - 1)) << 1) | (q & (jp - 1));
        int tp = ti | jp;
        bool up = ((ti & kp) == 0);
        float a = sk[li * 66 + ti], b = sk[li * 66 + tp];
        if ((a > b) == up) {
            sk[li * 66 + ti] = b; sk[li * 66 + tp] = a;
            int tv = sv[li * 66 + ti]; sv[li * 66 + ti] = sv[li * 66 + tp]; sv[li * 66 + tp] = tv;
        }
    }
    __syncthreads();
    for (int i = tid; i < 2048; i += 1024) {
        int li = i & 31, t = i >> 5;
        int idx = (low0 + li) + (t << 11);
        d_keys[idx] = sk[li * 66 + t];
        d_vals[idx] = sv[li * 66 + t];
    }
}

__global__ __launch_bounds__(1024) void bitonic_local_merge(int K) {
    __shared__ float sk[2048];
    __shared__ int   sv[2048];
    int base = blockIdx.x * 2048;
    int tid = threadIdx.x;
    sk[tid]        = d_keys[base + tid];        sv[tid]        = d_vals[base + tid];
    sk[tid + 1024] = d_keys[base + tid + 1024]; sv[tid + 1024] = d_vals[base + tid + 1024];
    for (int j = 1024; j > 0; j >>= 1) {
        __syncthreads();
        int i = ((tid & ~(j - 1)) << 1) | (tid & (j - 1));
        int p = i | j;
        bool up = (((base + i) & K) == 0);
        float a = sk[i], b = sk[p];
        if ((a > b) == up) {
            sk[i] = b; sk[p] = a;
            int t = sv[i]; sv[i] = sv[p]; sv[p] = t;
        }
    }
    __syncthreads();
    d_keys[base + tid]        = sk[tid];        d_vals[base + tid]        = sv[tid];
    d_keys[base + tid + 1024] = sk[tid + 1024]; d_vals[base + tid + 1024] = sv[tid + 1024];
}

__global__ void inverse_kernel(int n) {
    int r = blockIdx.x * blockDim.x + threadIdx.x;
    if (r < n) d_invp[d_vals[r]] = r;
}

// ---------------- conv1d (C=64, K=5, SAME); variant 1 fuses sorted-x gather ----------------
__global__ __launch_bounds__(1024) void conv_gather_kernel(const float* __restrict__ w,
                                                           const float* __restrict__ b,
                                                           float* __restrict__ outp, int n) {
    __shared__ float xs[68][64];
    __shared__ float ws[64][81];
    int tid = threadIdx.x;
    int l0 = blockIdx.x * 64;
    for (int i = tid; i < 68 * 64; i += 1024) {
        int r = i >> 6, c = i & 63;
        int g = l0 - 2 + r;
        float v = 0.f;
        if (g >= 0 && g < n)
            v = d_keys[g] * d_x1[(size_t)d_vals[g] * 64 + c];
        xs[r][c] = v;
    }
    int co = tid & 63;
    int grp = tid >> 6;
    int pb = grp << 2;
    float a0 = 0.f, a1 = 0.f, a2 = 0.f, a3 = 0.f;
    for (int cc = 0; cc < 64; cc += 16) {
        __syncthreads();
        for (int i = tid; i < 64 * 80; i += 1024) {
            int wco = i / 80;
            int rem = i - wco * 80;
            ws[wco][rem] = w[((size_t)wco * 64 + cc + rem / 5) * 5 + (rem % 5)];
        }
        __syncthreads();
        #pragma unroll
        for (int ci = 0; ci < 16; ci++) {
            float x0 = xs[pb+0][cc+ci], x1 = xs[pb+1][cc+ci], x2 = xs[pb+2][cc+ci],
                  x3 = xs[pb+3][cc+ci], x4 = xs[pb+4][cc+ci], x5 = xs[pb+5][cc+ci],
                  x6 = xs[pb+6][cc+ci], x7 = xs[pb+7][cc+ci];
            float w0 = ws[co][ci*5+0], w1 = ws[co][ci*5+1], w2 = ws[co][ci*5+2],
                  w3 = ws[co][ci*5+3], w4 = ws[co][ci*5+4];
            a0 += x0*w0 + x1*w1 + x2*w2 + x3*w3 + x4*w4;
            a1 += x1*w0 + x2*w1 + x3*w2 + x4*w3 + x5*w4;
            a2 += x2*w0 + x3*w1 + x4*w2 + x5*w3 + x6*w4;
            a3 += x3*w0 + x4*w1 + x5*w2 + x6*w3 + x7*w4;
        }
    }
    float bb = b[co];
    int gl = l0 + pb;
    float r0 = fmaxf(a0 + bb, 0.f), r1 = fmaxf(a1 + bb, 0.f);
    float r2 = fmaxf(a2 + bb, 0.f), r3 = fmaxf(a3 + bb, 0.f);
    if (gl + 0 < n) outp[(size_t)(gl+0)*64 + co] = r0;
    if (gl + 1 < n) outp[(size_t)(gl+1)*64 + co] = r1;
    if (gl + 2 < n) outp[(size_t)(gl+2)*64 + co] = r2;
    if (gl + 3 < n) outp[(size_t)(gl+3)*64 + co] = r3;
}

__global__ __launch_bounds__(1024) void conv_kernel(const float* __restrict__ xin,
                                                    const float* __restrict__ w,
                                                    const float* __restrict__ b,
                                                    float* __restrict__ outp, int n) {
    __shared__ float xs[68][64];
    __shared__ float ws[64][81];
    int tid = threadIdx.x;
    int l0 = blockIdx.x * 64;
    for (int i = tid; i < 68 * 64; i += 1024) {
        int r = i >> 6, c = i & 63;
        int g = l0 - 2 + r;
        xs[r][c] = (g >= 0 && g < n) ? xin[(size_t)g * 64 + c] : 0.f;
    }
    int co = tid & 63;
    int grp = tid >> 6;
    int pb = grp << 2;
    float a0 = 0.f, a1 = 0.f, a2 = 0.f, a3 = 0.f;
    for (int cc = 0; cc < 64; cc += 16) {
        __syncthreads();
        for (int i = tid; i < 64 * 80; i += 1024) {
            int wco = i / 80;
            int rem = i - wco * 80;
            ws[wco][rem] = w[((size_t)wco * 64 + cc + rem / 5) * 5 + (rem % 5)];
        }
        __syncthreads();
        #pragma unroll
        for (int ci = 0; ci < 16; ci++) {
            float x0 = xs[pb+0][cc+ci], x1 = xs[pb+1][cc+ci], x2 = xs[pb+2][cc+ci],
                  x3 = xs[pb+3][cc+ci], x4 = xs[pb+4][cc+ci], x5 = xs[pb+5][cc+ci],
                  x6 = xs[pb+6][cc+ci], x7 = xs[pb+7][cc+ci];
            float w0 = ws[co][ci*5+0], w1 = ws[co][ci*5+1], w2 = ws[co][ci*5+2],
                  w3 = ws[co][ci*5+3], w4 = ws[co][ci*5+4];
            a0 += x0*w0 + x1*w1 + x2*w2 + x3*w3 + x4*w4;
            a1 += x1*w0 + x2*w1 + x3*w2 + x4*w3 + x5*w4;
            a2 += x2*w0 + x3*w1 + x4*w2 + x5*w3 + x6*w4;
            a3 += x3*w0 + x4*w1 + x5*w2 + x6*w3 + x7*w4;
        }
    }
    float bb = b[co];
    int gl = l0 + pb;
    float r0 = a0 + bb, r1 = a1 + bb, r2 = a2 + bb, r3 = a3 + bb;
    if (gl + 0 < n) outp[(size_t)(gl+0)*64 + co] = r0;
    if (gl + 1 < n) outp[(size_t)(gl+1)*64 + co] = r1;
    if (gl + 2 < n) outp[(size_t)(gl+2)*64 + co] = r2;
    if (gl + 3 < n) outp[(size_t)(gl+3)*64 + co] = r3;
}

// ---------------- final: out = log_softmax([x1, x2] @ Wl + bl) ----------------
__global__ __launch_bounds__(256) void gemm3_kernel(const float* __restrict__ Wl,
                                                    const float* __restrict__ bl,
                                                    float* __restrict__ outp, int n) {
    __shared__ float As[16][64];
    __shared__ float Bs[16][64];
    __shared__ float Cs[64][65];
    int tid = threadIdx.x;
    int tx = tid & 15, ty = tid >> 4;
    int row0 = blockIdx.x * 64;
    int aRow = tid >> 2, aCol = (tid & 3) << 2;
    int bRow = tid >> 4, bCol = (tid & 15) << 2;
    ull acc[4][2];
    #pragma unroll
    for (int i = 0; i < 4; i++) { acc[i][0] = 0ull; acc[i][1] = 0ull; }
    int gr = row0 + aRow;
    int inv = (gr < n) ? d_invp[gr] : 0;
    for (int k0 = 0; k0 < 128; k0 += 16) {
        int kg = k0 + aCol;
        float4 av = make_float4(0,0,0,0);
        if (gr < n) {
            if (kg < 64) av = *(const float4*)(d_x1 + (size_t)gr * 64 + kg);
            else         av = *(const float4*)(d_c2 + (size_t)inv * 64 + (kg - 64));
        }
        float4 bv = *(const float4*)(Wl + (size_t)(k0 + bRow) * 64 + bCol);
        As[aCol+0][aRow]=av.x; As[aCol+1][aRow]=av.y; As[aCol+2][aRow]=av.z; As[aCol+3][aRow]=av.w;
        *(float4*)&Bs[bRow][bCol] = bv;
        __syncthreads();
        #pragma unroll
        for (int kk = 0; kk < 16; kk++) {
            float a[4];
            *(float4*)(a) = *(const float4*)&As[kk][ty<<2];
            ull b0 = *(const ull*)&Bs[kk][tx<<2];
            ull b1p = *(const ull*)&Bs[kk][(tx<<2) + 2];
            #pragma unroll
            for (int i = 0; i < 4; i++) {
                ull ai;
                PACK_DUP(ai, a[i]);
                FMA_F32X2(acc[i][0], ai, b0);
                FMA_F32X2(acc[i][1], ai, b1p);
            }
        }
        __syncthreads();
    }
    #pragma unroll
    for (int i = 0; i < 4; i++) {
        uint32_t lo, hi;
        float c0, c1v, c2v, c3v;
        UNPACK2(lo, hi, acc[i][0]); c0 = __uint_as_float(lo); c1v = __uint_as_float(hi);
        UNPACK2(lo, hi, acc[i][1]); c2v = __uint_as_float(lo); c3v = __uint_as_float(hi);
        int cb = tx << 2;
        Cs[(ty<<2)+i][cb+0] = c0  + bl[cb+0];
        Cs[(ty<<2)+i][cb+1] = c1v + bl[cb+1];
        Cs[(ty<<2)+i][cb+2] = c2v + bl[cb+2];
        Cs[(ty<<2)+i][cb+3] = c3v + bl[cb+3];
    }
    __syncthreads();
    if (tid < 64) {
        int grow = row0 + tid;
        if (grow < n) {
            float m = -3.0e38f;
            #pragma unroll
            for (int c = 0; c < 64; c++) m = fmaxf(m, Cs[tid][c]);
            float s = 0.f;
            #pragma unroll
            for (int c = 0; c < 64; c++) s += expf(Cs[tid][c] - m);
            float lse = m + logf(s);
            for (int c = 0; c < 64; c++)
                outp[(size_t)grow * 64 + c] = Cs[tid][c] - lse;
        }
    }
}

// ---------------- host launcher ----------------
extern "C" void kernel_launch(void* const* d_in, const int* in_sizes, int n_in,
                              void* d_out, int out_size) {
    const float* x   = (const float*)d_in[0];
    const void*  edg = d_in[1];
    const float* W1  = (const float*)d_in[2];
    const float* b1  = (const float*)d_in[3];
    const float* W2  = (const float*)d_in[4];
    const float* b2  = (const float*)d_in[5];
    const float* Wp  = (const float*)d_in[6];
    const float* bp  = (const float*)d_in[7];
    const float* cw1 = (const float*)d_in[8];
    const float* cb1 = (const float*)d_in[9];
    const float* cw2 = (const float*)d_in[10];
    const float* cb2 = (const float*)d_in[11];
    const float* Wl  = (const float*)d_in[12];
    const float* bl  = (const float*)d_in[13];
    float* out = (float*)d_out;

    int n = in_sizes[0] / FIN;
    int E = in_sizes[1] / 2;
    int G = (n + SCHUNK - 1) / SCHUNK;

    float *p_hw1, *p_agg1, *p_hw2, *p_c1, *p_c2;
    cudaGetSymbolAddress((void**)&p_hw1,  d_hw1);
    cudaGetSymbolAddress((void**)&p_agg1, d_agg1);
    cudaGetSymbolAddress((void**)&p_hw2,  d_hw2);
    cudaGetSymbolAddress((void**)&p_c1,   d_c1);
    cudaGetSymbolAddress((void**)&p_c2,   d_c2);

    // 0-2: edge prep
    detect_kernel<<<1, 1024>>>(edg, (long long)E, n);              // 0
    count_deg<<<(E + 255) / 256, 256>>>(edg, E);                   // 1
    compute_dinv<<<(n + 255) / 256, 256>>>(n);                     // 2

    // 3: gemm1 — profiled by ncu (clock canary: expect ~560us)
    gemm1_kernel<<<dim3((n + 63) / 64, HIDD / 64), 128>>>(x, W1, p_hw1, n);  // 3

    // CSR build
    scan_k1<<<G, 256>>>(n);
    scan_k2<<<1, 32>>>(G);
    scan_k3<<<G, 256>>>(n);
    scatter_kernel<<<(E + 255) / 256, 256>>>(edg, E);

    // GCN layer 1 aggregation — two feature-half passes (L2 blocking)
    csr_agg1_half<<<(n + 7) / 8, 256>>>(p_hw1, p_agg1, n, 0);
    csr_agg1_half<<<(n + 7) / 8, 256>>>(p_hw1, p_agg1, n, 32);

    // GCN layer 2 (bias+relu fused into A-load; dinv folded into epilogue)
    gemm2_kernel<<<(n + 63) / 64, 256>>>(p_agg1, b1, W2, p_hw2, n);
    csr_agg2<<<(n + 15) / 16, 256>>>(p_hw2, b2, Wp, bp, n);

    // argsort (fill fused into local sort)
    bitonic_local_sort_fill<<<MSORT / 2048, 1024>>>(n);
    for (int k = 4096; k <= MSORT; k <<= 1) {
        bitonic_strided<<<MSORT / 2048, 1024>>>(k >> 11);
        bitonic_local_merge<<<MSORT / 2048, 1024>>>(k);
    }
    inverse_kernel<<<(n + 255) / 256, 256>>>(n);

    // conv1d x2 (conv1 fuses sorted-x gather+scale)
    conv_gather_kernel<<<(n + 63) / 64, 1024>>>(cw1, cb1, p_c1, n);
    conv_kernel<<<(n + 63) / 64, 1024>>>(p_c1, cw2, cb2, p_c2, n);

    // final linear + log_softmax
    gemm3_kernel<<<(n + 63) / 64, 256>>>(Wl, bl, out, n);
}

// round 17
// speedup vs baseline: 1.5627x; 1.0160x over previous
#include <cuda_runtime.h>
#include <cuda_bf16.h>
#include <math.h>
#include <stdint.h>

#define NN    100000
#define FIN   512
#define HIDD  256
#define CCH   64
#define EMAX  3300000
#define MSORT 131072
#define SCHUNK 2048

typedef unsigned long long ull;

// packed fp32x2 FMA (Blackwell family-wide PTX; SASS FFMA2)
#define FMA_F32X2(d, a, b) \
    asm("fma.rn.f32x2 %0, %1, %2, %3;" : "=l"(d) : "l"(a), "l"(b), "l"(d))
#define PACK_DUP(out, v) \
    asm("mov.b64 %0, {%1, %1};" : "=l"(out) : "r"(__float_as_uint(v)))
#define PACK2(out, a, b) \
    asm("mov.b64 %0, {%1, %2};" : "=l"(out) : "r"(__float_as_uint(a)), "r"(__float_as_uint(b)))
#define UNPACK2(lo, hi, in) \
    asm("mov.b64 {%0, %1}, %2;" : "=r"(lo), "=r"(hi) : "l"(in))

// ---------------- scratch (device globals; no allocation) ----------------
__device__ float d_hw1 [(size_t)NN * HIDD];   // raw x@W1 (dinv applied in agg)
__device__ float d_agg1[(size_t)NN * HIDD];
__device__ float d_hw2 [(size_t)NN * CCH];    // y2 = dinv[r] * (relu(agg1+b1)@W2)[r]
__device__ float d_x1  [(size_t)NN * CCH];
__device__ float d_score[NN];
__device__ int   d_degi[NN];
__device__ float d_dinv[NN];
__device__ int   d_rowptr[NN + 1];
__device__ int   d_fill[NN];
__device__ int   d_part[256];
__device__ int   d_csri[EMAX];         // src index only
__device__ float d_keys[MSORT];
__device__ int   d_vals[MSORT];
__device__ int   d_invp[NN];
__device__ float d_c1  [(size_t)NN * CCH];
__device__ float d_c2  [(size_t)NN * CCH];
__device__ int   d_is64;

// ---------------- edge dtype detect + zero degrees ----------------
__global__ void detect_kernel(const void* edges, long long nElemsI64, int n) {
    for (int i = threadIdx.x; i < n; i += blockDim.x) d_degi[i] = 0;
    if (threadIdx.x == 0) {
        const long long* p = (const long long*)edges;
        int cnt = (int)(nElemsI64 < 256 ? nElemsI64 : 256);
        int ok = 1;
        for (int i = 0; i < cnt; i++) {
            long long v = p[i];
            if (v < 0 || v >= (long long)n) { ok = 0; break; }
        }
        d_is64 = ok;
    }
}

__global__ void count_deg(const void* edges, int E) {
    int e = blockIdx.x * blockDim.x + threadIdx.x;
    if (e >= E) return;
    int d;
    if (d_is64) d = (int)((const long long*)edges)[e + E];
    else        d = ((const int*)edges)[e + E];
    atomicAdd(&d_degi[d], 1);
}

__global__ void compute_dinv(int n) {
    int i = blockIdx.x * blockDim.x + threadIdx.x;
    if (i < n) d_dinv[i] = rsqrtf((float)(d_degi[i] + 1));
}

// ---------------- SGEMM 1: hw1 = x @ W1 (raw)   64x64 tile, 128 thr ----------------
__global__ __launch_bounds__(128) void gemm1_kernel(const float* __restrict__ A,
                                                    const float* __restrict__ B,
                                                    float* __restrict__ C, int n) {
    __shared__ float As[8][68];
    __shared__ float Bs[8][68];
    int tid = threadIdx.x;
    int row0 = blockIdx.x * 64;
    int col0 = blockIdx.y * 64;
    int aRow = tid >> 1;            // 0..63
    int aK   = (tid & 1) << 2;      // 0 or 4
    int bK   = tid >> 4;            // 0..7
    int bCol = (tid & 15) << 2;     // 0..60
    int ty = tid >> 4;              // 0..7
    int tx = tid & 15;              // 0..15
    int cr4 = ty << 2;              // rows cr4..+3 and +32
    int cc4 = tx << 2;              // cols cc4..+3
    ull acc[8][2];
    #pragma unroll
    for (int i = 0; i < 8; i++) { acc[i][0] = 0ull; acc[i][1] = 0ull; }
    int gr = row0 + aRow;
    for (int k0 = 0; k0 < FIN; k0 += 8) {
        float4 av = make_float4(0,0,0,0);
        if (gr < n) av = *(const float4*)(A + (size_t)gr * FIN + k0 + aK);
        float4 bv = *(const float4*)(B + (size_t)(k0 + bK) * HIDD + col0 + bCol);
        As[aK+0][aRow] = av.x; As[aK+1][aRow] = av.y;
        As[aK+2][aRow] = av.z; As[aK+3][aRow] = av.w;
        *(float4*)&Bs[bK][bCol] = bv;
        __syncthreads();
        #pragma unroll
        for (int kk = 0; kk < 8; kk++) {
            float a[8];
            *(float4*)(a)     = *(const float4*)&As[kk][cr4];
            *(float4*)(a + 4) = *(const float4*)&As[kk][cr4 + 32];
            float4 bq = *(const float4*)&Bs[kk][cc4];
            ull b0, b1;
            PACK2(b0, bq.x, bq.y);
            PACK2(b1, bq.z, bq.w);
            #pragma unroll
            for (int i = 0; i < 8; i++) {
                ull ai;
                PACK_DUP(ai, a[i]);
                FMA_F32X2(acc[i][0], ai, b0);
                FMA_F32X2(acc[i][1], ai, b1);
            }
        }
        __syncthreads();
    }
    #pragma unroll
    for (int i = 0; i < 8; i++) {
        int r = row0 + cr4 + (i & 3) + ((i >> 2) << 5);   // +0 or +32
        if (r < n) {
            uint32_t lo, hi;
            float c0, c1v, c2v, c3v;
            UNPACK2(lo, hi, acc[i][0]); c0  = __uint_as_float(lo); c1v = __uint_as_float(hi);
            UNPACK2(lo, hi, acc[i][1]); c2v = __uint_as_float(lo); c3v = __uint_as_float(hi);
            *(float4*)(C + (size_t)r * HIDD + col0 + cc4) = make_float4(c0, c1v, c2v, c3v);
        }
    }
}

// ---------------- CSR build: scan + scatter ----------------
__global__ void scan_k1(int n) {
    __shared__ int sh[256];
    int base = blockIdx.x * SCHUNK;
    int s = 0;
    for (int i = threadIdx.x; i < SCHUNK; i += 256) {
        int g = base + i;
        s += (g < n) ? d_degi[g] : 0;
    }
    sh[threadIdx.x] = s;
    __syncthreads();
    for (int o = 128; o; o >>= 1) {
        if (threadIdx.x < o) sh[threadIdx.x] += sh[threadIdx.x + o];
        __syncthreads();
    }
    if (threadIdx.x == 0) d_part[blockIdx.x] = sh[0];
}

__global__ void scan_k2(int G) {
    if (threadIdx.x == 0) {
        int acc = 0;
        for (int i = 0; i < G; i++) { int v = d_part[i]; d_part[i] = acc; acc += v; }
    }
}

__global__ void scan_k3(int n) {
    __shared__ int sh[256];
    int tid = threadIdx.x;
    int base = blockIdx.x * SCHUNK + tid * 8;
    int v[8], dg[8];
    int run = 0;
    #pragma unroll
    for (int j = 0; j < 8; j++) {
        int g = base + j;
        dg[j] = (g < n) ? d_degi[g] : 0;
        v[j] = run;
        run += dg[j];
    }
    sh[tid] = run;
    __syncthreads();
    for (int o = 1; o < 256; o <<= 1) {
        int t = (tid >= o) ? sh[tid - o] : 0;
        __syncthreads();
        sh[tid] += t;
        __syncthreads();
    }
    int off = d_part[blockIdx.x] + sh[tid] - run;
    #pragma unroll
    for (int j = 0; j < 8; j++) {
        int g = base + j;
        if (g < n) {
            int r = off + v[j];
            d_rowptr[g] = r;
            d_fill[g]   = r;
            if (g == n - 1) d_rowptr[n] = r + dg[j];
        }
    }
}

__global__ void scatter_kernel(const void* edges, int E) {
    int e = blockIdx.x * blockDim.x + threadIdx.x;
    if (e >= E) return;
    int s, d;
    if (d_is64) {
        const long long* p = (const long long*)edges;
        s = (int)p[e]; d = (int)p[e + E];
    } else {
        const int* p = (const int*)edges;
        s = p[e]; d = p[e + E];
    }
    int pos = atomicAdd(&d_fill[d], 1);
    d_csri[pos] = s;
}

// ---------------- CSR aggregation, layer 1 — feature-half pass (L2 blocking) ----------------
// agg1[d][f] = dinv[d] * ( dinv[d]*hw1[d][f] + sum_{s in N(d)} dinv[s]*hw1[s][f] )
__global__ __launch_bounds__(256) void csr_agg1_half(const float* __restrict__ y,
                                                     float* __restrict__ outp,
                                                     int n, int fo4) {
    int node = blockIdx.x * 8 + (threadIdx.x >> 5);
    int t = threadIdx.x & 31;
    if (node >= n) return;
    const float4* __restrict__ y4 = (const float4*)y;
    size_t base = (size_t)node * 64 + fo4 + t;
    float dvd = d_dinv[node];
    float4 yv = y4[base];
    float4 acc;
    acc.x = dvd * yv.x; acc.y = dvd * yv.y; acc.z = dvd * yv.z; acc.w = dvd * yv.w;
    int e   = d_rowptr[node];
    int end = d_rowptr[node + 1];
    for (; e + 4 <= end; e += 4) {
        int s0 = d_csri[e], s1 = d_csri[e+1], s2 = d_csri[e+2], s3 = d_csri[e+3];
        float dv0 = d_dinv[s0], dv1 = d_dinv[s1], dv2 = d_dinv[s2], dv3 = d_dinv[s3];
        float4 v0 = y4[(size_t)s0 * 64 + fo4 + t];
        float4 v1 = y4[(size_t)s1 * 64 + fo4 + t];
        float4 v2 = y4[(size_t)s2 * 64 + fo4 + t];
        float4 v3 = y4[(size_t)s3 * 64 + fo4 + t];
        acc.x += dv0*v0.x + dv1*v1.x + dv2*v2.x + dv3*v3.x;
        acc.y += dv0*v0.y + dv1*v1.y + dv2*v2.y + dv3*v3.y;
        acc.z += dv0*v0.z + dv1*v1.z + dv2*v2.z + dv3*v3.z;
        acc.w += dv0*v0.w + dv1*v1.w + dv2*v2.w + dv3*v3.w;
    }
    for (; e < end; e++) {
        int s = d_csri[e];
        float dv = d_dinv[s];
        float4 v = y4[(size_t)s * 64 + fo4 + t];
        acc.x += dv*v.x; acc.y += dv*v.y; acc.z += dv*v.z; acc.w += dv*v.w;
    }
    acc.x *= dvd; acc.y *= dvd; acc.z *= dvd; acc.w *= dvd;
    ((float4*)outp)[base] = acc;
}

// ---------------- SGEMM 2: y2 = dinv * (relu(agg1 + b1) @ W2), f32x2 ----------------
__global__ __launch_bounds__(256) void gemm2_kernel(const float* __restrict__ A,
                                                    const float* __restrict__ b1,
                                                    const float* __restrict__ B,
                                                    float* __restrict__ C, int n) {
    __shared__ float As[16][64];
    __shared__ float Bs[16][64];
    int tid = threadIdx.x;
    int tx = tid & 15, ty = tid >> 4;
    int row0 = blockIdx.x * 64;
    int aRow = tid >> 2, aCol = (tid & 3) << 2;
    int bRow = tid >> 4, bCol = (tid & 15) << 2;
    ull acc[4][2];
    #pragma unroll
    for (int i = 0; i < 4; i++) { acc[i][0] = 0ull; acc[i][1] = 0ull; }
    int gr = row0 + aRow;
    for (int k0 = 0; k0 < HIDD; k0 += 16) {
        float4 av = make_float4(0,0,0,0);
        if (gr < n) {
            av = *(const float4*)(A + (size_t)gr * HIDD + k0 + aCol);
            float4 bb = *(const float4*)(b1 + k0 + aCol);
            av.x = fmaxf(av.x + bb.x, 0.f);
            av.y = fmaxf(av.y + bb.y, 0.f);
            av.z = fmaxf(av.z + bb.z, 0.f);
            av.w = fmaxf(av.w + bb.w, 0.f);
        }
        float4 bv = *(const float4*)(B + (size_t)(k0 + bRow) * CCH + bCol);
        As[aCol+0][aRow]=av.x; As[aCol+1][aRow]=av.y; As[aCol+2][aRow]=av.z; As[aCol+3][aRow]=av.w;
        *(float4*)&Bs[bRow][bCol] = bv;
        __syncthreads();
        #pragma unroll
        for (int kk = 0; kk < 16; kk++) {
            float a[4];
            *(float4*)(a) = *(const float4*)&As[kk][ty<<2];
            ull b0 = *(const ull*)&Bs[kk][tx<<2];
            ull b1p = *(const ull*)&Bs[kk][(tx<<2) + 2];
            #pragma unroll
            for (int i = 0; i < 4; i++) {
                ull ai;
                PACK_DUP(ai, a[i]);
                FMA_F32X2(acc[i][0], ai, b0);
                FMA_F32X2(acc[i][1], ai, b1p);
            }
        }
        __syncthreads();
    }
    #pragma unroll
    for (int i = 0; i < 4; i++) {
        int r = row0 + (ty<<2) + i;
        if (r < n) {
            float dv = d_dinv[r];
            uint32_t lo, hi;
            float c0, c1v, c2v, c3v;
            UNPACK2(lo, hi, acc[i][0]); c0 = __uint_as_float(lo) * dv; c1v = __uint_as_float(hi) * dv;
            UNPACK2(lo, hi, acc[i][1]); c2v = __uint_as_float(lo) * dv; c3v = __uint_as_float(hi) * dv;
            *(float4*)(C + (size_t)r * CCH + (tx<<2)) = make_float4(c0, c1v, c2v, c3v);
        }
    }
}

// ---------------- CSR aggregation layer 2 fused with x1 = agg+b2 and score ----------------
__global__ __launch_bounds__(256) void csr_agg2(const float* __restrict__ y,
                                                const float* __restrict__ b2,
                                                const float* __restrict__ Wp,
                                                const float* __restrict__ bp, int n) {
    int node = blockIdx.x * 16 + (threadIdx.x >> 4);
    int t = threadIdx.x & 15;
    if (node >= n) return;
    const float4* __restrict__ y4 = (const float4*)y;
    float4 acc = y4[(size_t)node * 16 + t];
    int e   = d_rowptr[node];
    int end = d_rowptr[node + 1];
    for (; e + 4 <= end; e += 4) {
        int s0 = d_csri[e], s1 = d_csri[e+1], s2 = d_csri[e+2], s3 = d_csri[e+3];
        float4 v0 = y4[(size_t)s0 * 16 + t];
        float4 v1 = y4[(size_t)s1 * 16 + t];
        float4 v2 = y4[(size_t)s2 * 16 + t];
        float4 v3 = y4[(size_t)s3 * 16 + t];
        acc.x += v0.x + v1.x + v2.x + v3.x;
        acc.y += v0.y + v1.y + v2.y + v3.y;
        acc.z += v0.z + v1.z + v2.z + v3.z;
        acc.w += v0.w + v1.w + v2.w + v3.w;
    }
    for (; e < end; e++) {
        float4 v = y4[(size_t)d_csri[e] * 16 + t];
        acc.x += v.x; acc.y += v.y; acc.z += v.z; acc.w += v.w;
    }
    float dv = d_dinv[node];
    float4 bb = ((const float4*)b2)[t];
    acc.x = acc.x * dv + bb.x;
    acc.y = acc.y * dv + bb.y;
    acc.z = acc.z * dv + bb.z;
    acc.w = acc.w * dv + bb.w;
    ((float4*)d_x1)[(size_t)node * 16 + t] = acc;
    float4 wp = ((const float4*)Wp)[t];
    float p = acc.x*wp.x + acc.y*wp.y + acc.z*wp.z + acc.w*wp.w;
    unsigned gm = 0xFFFFu << (threadIdx.x & 16);
    #pragma unroll
    for (int o = 8; o; o >>= 1) p += __shfl_xor_sync(gm, p, o);
    if (t == 0) d_score[node] = p + bp[0];
}

// ---------------- bitonic argsort ----------------
__global__ __launch_bounds__(1024) void bitonic_local_sort_fill(int n) {
    __shared__ float sk[2048];
    __shared__ int   sv[2048];
    int base = blockIdx.x * 2048;
    int tid = threadIdx.x;
    int g0 = base + tid, g1 = base + tid + 1024;
    sk[tid]        = (g0 < n) ? d_score[g0] : 3.0e38f;  sv[tid]        = g0;
    sk[tid + 1024] = (g1 < n) ? d_score[g1] : 3.0e38f;  sv[tid + 1024] = g1;
    for (int k = 2; k <= 2048; k <<= 1) {
        for (int j = k >> 1; j > 0; j >>= 1) {
            __syncthreads();
            int i = ((tid & ~(j - 1)) << 1) | (tid & (j - 1));
            int p = i | j;
            bool up = (((base + i) & k) == 0);
            float a = sk[i], b = sk[p];
            if ((a > b) == up) {
                sk[i] = b; sk[p] = a;
                int t = sv[i]; sv[i] = sv[p]; sv[p] = t;
            }
        }
    }
    __syncthreads();
    d_keys[base + tid]        = sk[tid];        d_vals[base + tid]        = sv[tid];
    d_keys[base + tid + 1024] = sk[tid + 1024]; d_vals[base + tid + 1024] = sv[tid + 1024];
}

__global__ __launch_bounds__(1024) void bitonic_strided(int kp) {
    __shared__ float sk[32 * 66];
    __shared__ int   sv[32 * 66];
    int tid = threadIdx.x;
    int low0 = blockIdx.x * 32;
    for (int i = tid; i < 2048; i += 1024) {
        int li = i & 31, t = i >> 5;
        int idx = (low0 + li) + (t << 11);
        sk[li * 66 + t] = d_keys[idx];
        sv[li * 66 + t] = d_vals[idx];
    }
    for (int jp = kp >> 1; jp > 0; jp >>= 1) {
        __syncthreads();
        int li = tid >> 5, q = tid & 31;
        int ti = ((q & ~(jp - 1)) << 1) | (q & (jp - 1));
        int tp = ti | jp;
        bool up = ((ti & kp) == 0);
        float a = sk[li * 66 + ti], b = sk[li * 66 + tp];
        if ((a > b) == up) {
            sk[li * 66 + ti] = b; sk[li * 66 + tp] = a;
            int tv = sv[li * 66 + ti]; sv[li * 66 + ti] = sv[li * 66 + tp]; sv[li * 66 + tp] = tv;
        }
    }
    __syncthreads();
    for (int i = tid; i < 2048; i += 1024) {
        int li = i & 31, t = i >> 5;
        int idx = (low0 + li) + (t << 11);
        d_keys[idx] = sk[li * 66 + t];
        d_vals[idx] = sv[li * 66 + t];
    }
}

__global__ __launch_bounds__(1024) void bitonic_local_merge(int K) {
    __shared__ float sk[2048];
    __shared__ int   sv[2048];
    int base = blockIdx.x * 2048;
    int tid = threadIdx.x;
    sk[tid]        = d_keys[base + tid];        sv[tid]        = d_vals[base + tid];
    sk[tid + 1024] = d_keys[base + tid + 1024]; sv[tid + 1024] = d_vals[base + tid + 1024];
    for (int j = 1024; j > 0; j >>= 1) {
        __syncthreads();
        int i = ((tid & ~(j - 1)) << 1) | (tid & (j - 1));
        int p = i | j;
        bool up = (((base + i) & K) == 0);
        float a = sk[i], b = sk[p];
        if ((a > b) == up) {
            sk[i] = b; sk[p] = a;
            int t = sv[i]; sv[i] = sv[p]; sv[p] = t;
        }
    }
    __syncthreads();
    d_keys[base + tid]        = sk[tid];        d_vals[base + tid]        = sv[tid];
    d_keys[base + tid + 1024] = sk[tid + 1024]; d_vals[base + tid + 1024] = sv[tid + 1024];
}

__global__ void inverse_kernel(int n) {
    int r = blockIdx.x * blockDim.x + threadIdx.x;
    if (r < n) d_invp[d_vals[r]] = r;
}

// ---------------- conv1d (C=64, K=5, SAME); variant 1 fuses sorted-x gather ----------------
__global__ __launch_bounds__(1024) void conv_gather_kernel(const float* __restrict__ w,
                                                           const float* __restrict__ b,
                                                           float* __restrict__ outp, int n) {
    __shared__ float xs[68][64];
    __shared__ float ws[64][81];
    int tid = threadIdx.x;
    int l0 = blockIdx.x * 64;
    for (int i = tid; i < 68 * 64; i += 1024) {
        int r = i >> 6, c = i & 63;
        int g = l0 - 2 + r;
        float v = 0.f;
        if (g >= 0 && g < n)
            v = d_keys[g] * d_x1[(size_t)d_vals[g] * 64 + c];
        xs[r][c] = v;
    }
    int co = tid & 63;
    int grp = tid >> 6;
    int pb = grp << 2;
    float a0 = 0.f, a1 = 0.f, a2 = 0.f, a3 = 0.f;
    for (int cc = 0; cc < 64; cc += 16) {
        __syncthreads();
        for (int i = tid; i < 64 * 80; i += 1024) {
            int wco = i / 80;
            int rem = i - wco * 80;
            ws[wco][rem] = w[((size_t)wco * 64 + cc + rem / 5) * 5 + (rem % 5)];
        }
        __syncthreads();
        #pragma unroll
        for (int ci = 0; ci < 16; ci++) {
            float x0 = xs[pb+0][cc+ci], x1 = xs[pb+1][cc+ci], x2 = xs[pb+2][cc+ci],
                  x3 = xs[pb+3][cc+ci], x4 = xs[pb+4][cc+ci], x5 = xs[pb+5][cc+ci],
                  x6 = xs[pb+6][cc+ci], x7 = xs[pb+7][cc+ci];
            float w0 = ws[co][ci*5+0], w1 = ws[co][ci*5+1], w2 = ws[co][ci*5+2],
                  w3 = ws[co][ci*5+3], w4 = ws[co][ci*5+4];
            a0 += x0*w0 + x1*w1 + x2*w2 + x3*w3 + x4*w4;
            a1 += x1*w0 + x2*w1 + x3*w2 + x4*w3 + x5*w4;
            a2 += x2*w0 + x3*w1 + x4*w2 + x5*w3 + x6*w4;
            a3 += x3*w0 + x4*w1 + x5*w2 + x6*w3 + x7*w4;
        }
    }
    float bb = b[co];
    int gl = l0 + pb;
    float r0 = fmaxf(a0 + bb, 0.f), r1 = fmaxf(a1 + bb, 0.f);
    float r2 = fmaxf(a2 + bb, 0.f), r3 = fmaxf(a3 + bb, 0.f);
    if (gl + 0 < n) outp[(size_t)(gl+0)*64 + co] = r0;
    if (gl + 1 < n) outp[(size_t)(gl+1)*64 + co] = r1;
    if (gl + 2 < n) outp[(size_t)(gl+2)*64 + co] = r2;
    if (gl + 3 < n) outp[(size_t)(gl+3)*64 + co] = r3;
}

__global__ __launch_bounds__(1024) void conv_kernel(const float* __restrict__ xin,
                                                    const float* __restrict__ w,
                                                    const float* __restrict__ b,
                                                    float* __restrict__ outp, int n) {
    __shared__ float xs[68][64];
    __shared__ float ws[64][81];
    int tid = threadIdx.x;
    int l0 = blockIdx.x * 64;
    for (int i = tid; i < 68 * 64; i += 1024) {
        int r = i >> 6, c = i & 63;
        int g = l0 - 2 + r;
        xs[r][c] = (g >= 0 && g < n) ? xin[(size_t)g * 64 + c] : 0.f;
    }
    int co = tid & 63;
    int grp = tid >> 6;
    int pb = grp << 2;
    float a0 = 0.f, a1 = 0.f, a2 = 0.f, a3 = 0.f;
    for (int cc = 0; cc < 64; cc += 16) {
        __syncthreads();
        for (int i = tid; i < 64 * 80; i += 1024) {
            int wco = i / 80;
            int rem = i - wco * 80;
            ws[wco][rem] = w[((size_t)wco * 64 + cc + rem / 5) * 5 + (rem % 5)];
        }
        __syncthreads();
        #pragma unroll
        for (int ci = 0; ci < 16; ci++) {
            float x0 = xs[pb+0][cc+ci], x1 = xs[pb+1][cc+ci], x2 = xs[pb+2][cc+ci],
                  x3 = xs[pb+3][cc+ci], x4 = xs[pb+4][cc+ci], x5 = xs[pb+5][cc+ci],
                  x6 = xs[pb+6][cc+ci], x7 = xs[pb+7][cc+ci];
            float w0 = ws[co][ci*5+0], w1 = ws[co][ci*5+1], w2 = ws[co][ci*5+2],
                  w3 = ws[co][ci*5+3], w4 = ws[co][ci*5+4];
            a0 += x0*w0 + x1*w1 + x2*w2 + x3*w3 + x4*w4;
            a1 += x1*w0 + x2*w1 + x3*w2 + x4*w3 + x5*w4;
            a2 += x2*w0 + x3*w1 + x4*w2 + x5*w3 + x6*w4;
            a3 += x3*w0 + x4*w1 + x5*w2 + x6*w3 + x7*w4;
        }
    }
    float bb = b[co];
    int gl = l0 + pb;
    float r0 = a0 + bb, r1 = a1 + bb, r2 = a2 + bb, r3 = a3 + bb;
    if (gl + 0 < n) outp[(size_t)(gl+0)*64 + co] = r0;
    if (gl + 1 < n) outp[(size_t)(gl+1)*64 + co] = r1;
    if (gl + 2 < n) outp[(size_t)(gl+2)*64 + co] = r2;
    if (gl + 3 < n) outp[(size_t)(gl+3)*64 + co] = r3;
}

// ---------------- final: out = log_softmax([x1, x2] @ Wl + bl) ----------------
__global__ __launch_bounds__(256) void gemm3_kernel(const float* __restrict__ Wl,
                                                    const float* __restrict__ bl,
                                                    float* __restrict__ outp, int n) {
    __shared__ float As[16][64];
    __shared__ float Bs[16][64];
    __shared__ float Cs[64][65];
    int tid = threadIdx.x;
    int tx = tid & 15, ty = tid >> 4;
    int row0 = blockIdx.x * 64;
    int aRow = tid >> 2, aCol = (tid & 3) << 2;
    int bRow = tid >> 4, bCol = (tid & 15) << 2;
    ull acc[4][2];
    #pragma unroll
    for (int i = 0; i < 4; i++) { acc[i][0] = 0ull; acc[i][1] = 0ull; }
    int gr = row0 + aRow;
    int inv = (gr < n) ? d_invp[gr] : 0;
    for (int k0 = 0; k0 < 128; k0 += 16) {
        int kg = k0 + aCol;
        float4 av = make_float4(0,0,0,0);
        if (gr < n) {
            if (kg < 64) av = *(const float4*)(d_x1 + (size_t)gr * 64 + kg);
            else         av = *(const float4*)(d_c2 + (size_t)inv * 64 + (kg - 64));
        }
        float4 bv = *(const float4*)(Wl + (size_t)(k0 + bRow) * 64 + bCol);
        As[aCol+0][aRow]=av.x; As[aCol+1][aRow]=av.y; As[aCol+2][aRow]=av.z; As[aCol+3][aRow]=av.w;
        *(float4*)&Bs[bRow][bCol] = bv;
        __syncthreads();
        #pragma unroll
        for (int kk = 0; kk < 16; kk++) {
            float a[4];
            *(float4*)(a) = *(const float4*)&As[kk][ty<<2];
            ull b0 = *(const ull*)&Bs[kk][tx<<2];
            ull b1p = *(const ull*)&Bs[kk][(tx<<2) + 2];
            #pragma unroll
            for (int i = 0; i < 4; i++) {
                ull ai;
                PACK_DUP(ai, a[i]);
                FMA_F32X2(acc[i][0], ai, b0);
                FMA_F32X2(acc[i][1], ai, b1p);
            }
        }
        __syncthreads();
    }
    #pragma unroll
    for (int i = 0; i < 4; i++) {
        uint32_t lo, hi;
        float c0, c1v, c2v, c3v;
        UNPACK2(lo, hi, acc[i][0]); c0 = __uint_as_float(lo); c1v = __uint_as_float(hi);
        UNPACK2(lo, hi, acc[i][1]); c2v = __uint_as_float(lo); c3v = __uint_as_float(hi);
        int cb = tx << 2;
        Cs[(ty<<2)+i][cb+0] = c0  + bl[cb+0];
        Cs[(ty<<2)+i][cb+1] = c1v + bl[cb+1];
        Cs[(ty<<2)+i][cb+2] = c2v + bl[cb+2];
        Cs[(ty<<2)+i][cb+3] = c3v + bl[cb+3];
    }
    __syncthreads();
    if (tid < 64) {
        int grow = row0 + tid;
        if (grow < n) {
            float m = -3.0e38f;
            #pragma unroll
            for (int c = 0; c < 64; c++) m = fmaxf(m, Cs[tid][c]);
            float s = 0.f;
            #pragma unroll
            for (int c = 0; c < 64; c++) s += expf(Cs[tid][c] - m);
            float lse = m + logf(s);
            for (int c = 0; c < 64; c++)
                outp[(size_t)grow * 64 + c] = Cs[tid][c] - lse;
        }
    }
}

// ---------------- host launcher ----------------
extern "C" void kernel_launch(void* const* d_in, const int* in_sizes, int n_in,
                              void* d_out, int out_size) {
    const float* x   = (const float*)d_in[0];
    const void*  edg = d_in[1];
    const float* W1  = (const float*)d_in[2];
    const float* b1  = (const float*)d_in[3];
    const float* W2  = (const float*)d_in[4];
    const float* b2  = (const float*)d_in[5];
    const float* Wp  = (const float*)d_in[6];
    const float* bp  = (const float*)d_in[7];
    const float* cw1 = (const float*)d_in[8];
    const float* cb1 = (const float*)d_in[9];
    const float* cw2 = (const float*)d_in[10];
    const float* cb2 = (const float*)d_in[11];
    const float* Wl  = (const float*)d_in[12];
    const float* bl  = (const float*)d_in[13];
    float* out = (float*)d_out;

    int n = in_sizes[0] / FIN;
    int E = in_sizes[1] / 2;
    int G = (n + SCHUNK - 1) / SCHUNK;

    float *p_hw1, *p_agg1, *p_hw2, *p_c1, *p_c2;
    cudaGetSymbolAddress((void**)&p_hw1,  d_hw1);
    cudaGetSymbolAddress((void**)&p_agg1, d_agg1);
    cudaGetSymbolAddress((void**)&p_hw2,  d_hw2);
    cudaGetSymbolAddress((void**)&p_c1,   d_c1);
    cudaGetSymbolAddress((void**)&p_c2,   d_c2);

    // fork: side stream runs edge prep + CSR build concurrently with gemm1
    cudaStream_t s2;
    cudaStreamCreateWithFlags(&s2, cudaStreamNonBlocking);
    cudaEvent_t evFork, evJoin;
    cudaEventCreateWithFlags(&evFork, cudaEventDisableTiming);
    cudaEventCreateWithFlags(&evJoin, cudaEventDisableTiming);

    cudaEventRecord(evFork, 0);
    cudaStreamWaitEvent(s2, evFork, 0);

    // stream B: full prep chain
    detect_kernel<<<1, 1024, 0, s2>>>(edg, (long long)E, n);
    count_deg<<<(E + 255) / 256, 256, 0, s2>>>(edg, E);
    compute_dinv<<<(n + 255) / 256, 256, 0, s2>>>(n);
    scan_k1<<<G, 256, 0, s2>>>(n);
    scan_k2<<<1, 32, 0, s2>>>(G);
    scan_k3<<<G, 256, 0, s2>>>(n);
    scatter_kernel<<<(E + 255) / 256, 256, 0, s2>>>(edg, E);

    // main stream: gemm1 (raw, no dinv dependency) runs concurrently
    gemm1_kernel<<<dim3((n + 63) / 64, HIDD / 64), 128>>>(x, W1, p_hw1, n);

    // join
    cudaEventRecord(evJoin, s2);
    cudaStreamWaitEvent(0, evJoin, 0);

    // GCN layer 1 aggregation — two feature-half passes (L2 blocking; dinv fused)
    csr_agg1_half<<<(n + 7) / 8, 256>>>(p_hw1, p_agg1, n, 0);
    csr_agg1_half<<<(n + 7) / 8, 256>>>(p_hw1, p_agg1, n, 32);

    // GCN layer 2 (bias+relu fused into A-load; dinv folded into epilogue)
    gemm2_kernel<<<(n + 63) / 64, 256>>>(p_agg1, b1, W2, p_hw2, n);
    csr_agg2<<<(n + 15) / 16, 256>>>(p_hw2, b2, Wp, bp, n);

    // argsort (fill fused into local sort)
    bitonic_local_sort_fill<<<MSORT / 2048, 1024>>>(n);
    for (int k = 4096; k <= MSORT; k <<= 1) {
        bitonic_strided<<<MSORT / 2048, 1024>>>(k >> 11);
        bitonic_local_merge<<<MSORT / 2048, 1024>>>(k);
    }
    inverse_kernel<<<(n + 255) / 256, 256>>>(n);

    // conv1d x2 (conv1 fuses sorted-x gather+scale)
    conv_gather_kernel<<<(n + 63) / 64, 1024>>>(cw1, cb1, p_c1, n);
    conv_kernel<<<(n + 63) / 64, 1024>>>(p_c1, cw2, cb2, p_c2, n);

    // final linear + log_softmax
    gemm3_kernel<<<(n + 63) / 64, 256>>>(Wl, bl, out, n);

    cudaEventDestroy(evFork);
    cudaEventDestroy(evJoin);
    cudaStreamDestroy(s2);
}